// round 6
// baseline (speedup 1.0000x reference)
#include <cuda_runtime.h>

// NormalShader fused, R6: phase-pipelined 2 pixels/thread so both gather
// chains overlap (front-batched LDGs), slow path reloads rows cache-hot.

#define K_SAMP 8
#define BLK 256
#define PPT 2
#define F_MAX 200000

__device__ float4 g_packed[F_MAX * 3];   // 9.6 MB, L2-resident

__global__ __launch_bounds__(256)
void pack_faces_kernel(const int*   __restrict__ faces,
                       const float* __restrict__ vnorm,
                       int total)                  // total = F*3
{
    int j = blockIdx.x * blockDim.x + threadIdx.x;
    if (j >= total) return;
    int v = faces[j];
    const float* n = vnorm + v * 3;
    g_packed[j] = make_float4(n[0], n[1], n[2], 0.0f);
}

__global__ __launch_bounds__(BLK, 5)
void normal_shader_kernel(const int*   __restrict__ p2f,
                          const float* __restrict__ bary,
                          const float* __restrict__ zbuf,
                          const float* __restrict__ dists,
                          float*       __restrict__ out,
                          int npix)
{
    __shared__ float s[BLK * PPT * 3];

    const float ZFAR = 100.0f;
    const float INV_ZRANGE = 1.0f / 99.0f;
    const float INV_SIGMA = 1.0e4f;
    const float INV_GAMMA = 1.0e4f;
    const float EPS = 1.0e-10f;
    const float BGDIR = 0.577350269f;

    int tid  = threadIdx.x;
    int base = blockIdx.x * (BLK * PPT);

    int   pixc[PPT];
    float zmax[PPT];
    int   ksel[PPT];
    int   fsel[PPT];
    bool  ties[PPT];
    bool  valid[PPT];

    // ================= PHASE 1+2: rows, argmax, tie-detect =================
    #pragma unroll
    for (int p = 0; p < PPT; p++) {
        int pix = base + p * BLK + tid;
        pixc[p] = (pix < npix) ? pix : 0;

        int4   fa = reinterpret_cast<const int4*  >(p2f )[pixc[p] * 2 + 0];
        int4   fb = reinterpret_cast<const int4*  >(p2f )[pixc[p] * 2 + 1];
        float4 za = reinterpret_cast<const float4*>(zbuf)[pixc[p] * 2 + 0];
        float4 zb = reinterpret_cast<const float4*>(zbuf)[pixc[p] * 2 + 1];

        int   pf[K_SAMP] = {fa.x, fa.y, fa.z, fa.w, fb.x, fb.y, fb.z, fb.w};
        float zv[K_SAMP] = {za.x, za.y, za.z, za.w, zb.x, zb.y, zb.z, zb.w};

        float zm = 0.0f; int ks = -1; int fs = 0;
        #pragma unroll
        for (int k = 0; k < K_SAMP; k++) {
            float zi = (pf[k] >= 0) ? (ZFAR - zv[k]) * INV_ZRANGE : 0.0f;
            if (zi > zm) { zm = zi; ks = k; fs = pf[k]; }
        }
        float thresh = zm - 1.5e-3f;
        bool t = false;
        #pragma unroll
        for (int k = 0; k < K_SAMP; k++) {
            float zi = (pf[k] >= 0) ? (ZFAR - zv[k]) * INV_ZRANGE : 0.0f;
            t |= (k != ks && pf[k] >= 0 && zi > thresh);
        }
        zmax[p] = zm; ksel[p] = ks; fsel[p] = fs;
        ties[p] = t;  valid[p] = (ks >= 0);
        // pf/zv die here -> low live-register pressure across phases
    }

    // ================= PHASE 3: batched gathers for both pixels =============
    float4 q0[PPT], q1[PPT], q2[PPT];
    float  b0[PPT], b1[PPT], b2[PPT];
    #pragma unroll
    for (int p = 0; p < PPT; p++) {
        int f = valid[p] ? fsel[p] : 0;
        q0[p] = g_packed[f * 3 + 0];
        q1[p] = g_packed[f * 3 + 1];
        q2[p] = g_packed[f * 3 + 2];
        int bb = (pixc[p] * K_SAMP + (valid[p] ? ksel[p] : 0)) * 3;
        b0[p] = bary[bb + 0];
        b1[p] = bary[bb + 1];
        b2[p] = bary[bb + 2];
    }

    // ================= PHASE 4: compute + rare slow path ====================
    #pragma unroll
    for (int p = 0; p < PPT; p++) {
        float vx, vy, vz;
        if (!valid[p]) {
            vx = BGDIR; vy = BGDIR; vz = BGDIR;
        } else if (!ties[p] && zmax[p] >= 2.4e-3f) {
            // FAST: single contributor; prob & denom cancel in normalize
            vx = fmaf(b0[p], q0[p].x, fmaf(b1[p], q1[p].x, b2[p] * q2[p].x));
            vy = fmaf(b0[p], q0[p].y, fmaf(b1[p], q1[p].y, b2[p] * q2[p].y));
            vz = fmaf(b0[p], q0[p].z, fmaf(b1[p], q1[p].z, b2[p] * q2[p].z));
        } else {
            // SLOW (rare): reload rows (L1/L2-hot), full softmax blend
            int4   fa = reinterpret_cast<const int4*  >(p2f )[pixc[p] * 2 + 0];
            int4   fb = reinterpret_cast<const int4*  >(p2f )[pixc[p] * 2 + 1];
            float4 za = reinterpret_cast<const float4*>(zbuf)[pixc[p] * 2 + 0];
            float4 zb = reinterpret_cast<const float4*>(zbuf)[pixc[p] * 2 + 1];
            float4 da = reinterpret_cast<const float4*>(dists)[pixc[p] * 2 + 0];
            float4 db = reinterpret_cast<const float4*>(dists)[pixc[p] * 2 + 1];

            int   pf[K_SAMP] = {fa.x, fa.y, fa.z, fa.w, fb.x, fb.y, fb.z, fb.w};
            float zv[K_SAMP] = {za.x, za.y, za.z, za.w, zb.x, zb.y, zb.z, zb.w};
            float dv[K_SAMP] = {da.x, da.y, da.z, da.w, db.x, db.y, db.z, db.w};

            float zm = fmaxf(zmax[p], EPS);
            float delta = EPS;
            if (zmax[p] < 2.4e-3f)
                delta = fmaxf(__expf((EPS - zm) * INV_GAMMA), EPS);

            float ax = 0.0f, ay = 0.0f, az = 0.0f;
            float lim = zm - 3.0e-3f;
            #pragma unroll
            for (int k = 0; k < K_SAMP; k++) {
                if (pf[k] < 0) continue;
                float zi = (ZFAR - zv[k]) * INV_ZRANGE;
                if (zi <= lim) continue;
                float ew = __expf((zi - zm) * INV_GAMMA);
                float prob = 1.0f / (1.0f + __expf(dv[k] * INV_SIGMA));
                float w = prob * ew;

                int ff = pf[k];
                float4 m0 = g_packed[ff * 3 + 0];
                float4 m1 = g_packed[ff * 3 + 1];
                float4 m2 = g_packed[ff * 3 + 2];

                int bk = (pixc[p] * K_SAMP + k) * 3;
                float c0 = bary[bk + 0];
                float c1 = bary[bk + 1];
                float c2 = bary[bk + 2];

                float gx = fmaf(c0, m0.x, fmaf(c1, m1.x, c2 * m2.x));
                float gy = fmaf(c0, m0.y, fmaf(c1, m1.y, c2 * m2.y));
                float gz = fmaf(c0, m0.z, fmaf(c1, m1.z, c2 * m2.z));

                ax = fmaf(w, gx, ax);
                ay = fmaf(w, gy, ay);
                az = fmaf(w, gz, az);
            }
            vx = ax + delta;
            vy = ay + delta;
            vz = az + delta;
        }

        // normalize + map to [0,1], stage in smem
        float nn  = fmaf(vx, vx, fmaf(vy, vy, vz * vz));
        float inv = rsqrtf(fmaxf(nn, 1e-24f));
        int si = (p * BLK + tid) * 3;
        s[si + 0] = fmaf(vx * inv, 0.5f, 0.5f);
        s[si + 1] = fmaf(vy * inv, 0.5f, 0.5f);
        s[si + 2] = fmaf(vz * inv, 0.5f, 0.5f);
    }

    __syncthreads();

    // ---- coalesced float4 stores ----
    const int NF  = BLK * PPT * 3;       // 1536 floats
    const int NV4 = NF / 4;              // 384
    long fbase  = (long)blockIdx.x * NF;
    long ftotal = (long)npix * 3;
    if (fbase + NF <= ftotal) {
        #pragma unroll
        for (int i = tid; i < NV4; i += BLK) {
            reinterpret_cast<float4*>(out)[fbase / 4 + i] =
                reinterpret_cast<const float4*>(s)[i];
        }
    } else {
        for (int i = tid; i < NF; i += BLK) {
            long fi = fbase + i;
            if (fi < ftotal) out[fi] = s[i];
        }
    }
}

extern "C" void kernel_launch(void* const* d_in, const int* in_sizes, int n_in,
                              void* d_out, int out_size)
{
    const int*   p2f   = (const int*  )d_in[0];
    const float* bary  = (const float*)d_in[1];
    const float* zbuf  = (const float*)d_in[2];
    const float* dists = (const float*)d_in[3];
    const float* vnorm = (const float*)d_in[4];
    const int*   faces = (const int*  )d_in[5];
    float* out = (float*)d_out;

    int total = in_sizes[5];                 // F*3
    if (total > F_MAX * 3) total = F_MAX * 3;
    int npix = in_sizes[0] / K_SAMP;

    pack_faces_kernel<<<(total + 255) / 256, 256>>>(faces, vnorm, total);

    int blocks = (npix + BLK * PPT - 1) / (BLK * PPT);
    normal_shader_kernel<<<blocks, BLK>>>(p2f, bary, zbuf, dists, out, npix);
}

// round 7
// speedup vs baseline: 1.6304x; 1.6304x over previous
#include <cuda_runtime.h>

// NormalShader fused, R7: R5 structure, PPT=1 (low regs / high occ),
// streaming cache hints on read-once streams so L2 keeps the face table.

#define K_SAMP 8
#define BLK 256
#define F_MAX 200000

__device__ float4 g_packed[F_MAX * 3];   // 9.6 MB, L2-resident

__global__ __launch_bounds__(256)
void pack_faces_kernel(const int*   __restrict__ faces,
                       const float* __restrict__ vnorm,
                       int total)                  // total = F*3
{
    int j = blockIdx.x * blockDim.x + threadIdx.x;
    if (j >= total) return;
    int v = faces[j];
    const float* n = vnorm + v * 3;
    g_packed[j] = make_float4(n[0], n[1], n[2], 0.0f);
}

__global__ __launch_bounds__(BLK, 6)
void normal_shader_kernel(const int*   __restrict__ p2f,
                          const float* __restrict__ bary,
                          const float* __restrict__ zbuf,
                          const float* __restrict__ dists,
                          float*       __restrict__ out,
                          int npix)
{
    __shared__ float s[BLK * 3];

    const float ZFAR = 100.0f;
    const float INV_ZRANGE = 1.0f / 99.0f;
    const float INV_SIGMA = 1.0e4f;
    const float INV_GAMMA = 1.0e4f;
    const float EPS = 1.0e-10f;
    const float BGDIR = 0.577350269f;

    int tid = threadIdx.x;
    int pix = blockIdx.x * BLK + tid;
    int pixc = (pix < npix) ? pix : 0;

    // ---- streaming row loads (read-once; keep L2 for the face table) ----
    int4   f0 = __ldcs(reinterpret_cast<const int4*  >(p2f ) + pixc * 2 + 0);
    int4   f1 = __ldcs(reinterpret_cast<const int4*  >(p2f ) + pixc * 2 + 1);
    float4 z0 = __ldcs(reinterpret_cast<const float4*>(zbuf) + pixc * 2 + 0);
    float4 z1 = __ldcs(reinterpret_cast<const float4*>(zbuf) + pixc * 2 + 1);

    int   pf[K_SAMP] = {f0.x, f0.y, f0.z, f0.w, f1.x, f1.y, f1.z, f1.w};
    float zv[K_SAMP] = {z0.x, z0.y, z0.z, z0.w, z1.x, z1.y, z1.z, z1.w};

    // ---- z_inv + argmax (track face id: no dynamic reg indexing) ----
    float zinv[K_SAMP];
    float zmax = 0.0f;
    int   ksel = -1;
    int   fsel = 0;
    #pragma unroll
    for (int k = 0; k < K_SAMP; k++) {
        float zi = (pf[k] >= 0) ? (ZFAR - zv[k]) * INV_ZRANGE : 0.0f;
        zinv[k] = zi;
        if (zi > zmax) { zmax = zi; ksel = k; fsel = pf[k]; }
    }
    bool valid = (ksel >= 0);

    // ---- unconditional gather for argmax sample: 3 x LDG.128 + bary ----
    int f  = valid ? fsel : 0;
    float4 q0 = g_packed[f * 3 + 0];
    float4 q1 = g_packed[f * 3 + 1];
    float4 q2 = g_packed[f * 3 + 2];

    int bb = (pixc * K_SAMP + (valid ? ksel : 0)) * 3;
    float b0 = bary[bb + 0];
    float b1 = bary[bb + 1];
    float b2 = bary[bb + 2];

    float nx = fmaf(b0, q0.x, fmaf(b1, q1.x, b2 * q2.x));
    float ny = fmaf(b0, q0.y, fmaf(b1, q1.y, b2 * q2.y));
    float nz = fmaf(b0, q0.z, fmaf(b1, q1.z, b2 * q2.z));

    // ---- near-tie detection ----
    float thresh = zmax - 1.5e-3f;
    bool ties = false;
    #pragma unroll
    for (int k = 0; k < K_SAMP; k++)
        ties |= (k != ksel && pf[k] >= 0 && zinv[k] > thresh);

    float vx, vy, vz;
    if (!valid) {
        vx = BGDIR; vy = BGDIR; vz = BGDIR;      // all background
    } else if (!ties && zmax >= 2.4e-3f) {
        // FAST: single contributor; prob & denom cancel in normalize
        vx = nx; vy = ny; vz = nz;
    } else {
        // SLOW (rare): full weights for samples within 3e-3 of max
        float zm = fmaxf(zmax, EPS);
        float delta = EPS;
        if (zmax < 2.4e-3f)
            delta = fmaxf(__expf((EPS - zm) * INV_GAMMA), EPS);

        float4 d0 = __ldcs(reinterpret_cast<const float4*>(dists) + pixc * 2 + 0);
        float4 d1 = __ldcs(reinterpret_cast<const float4*>(dists) + pixc * 2 + 1);
        float dv[K_SAMP] = {d0.x, d0.y, d0.z, d0.w, d1.x, d1.y, d1.z, d1.w};

        float ax = 0.0f, ay = 0.0f, az = 0.0f;
        float lim = zm - 3.0e-3f;
        #pragma unroll
        for (int k = 0; k < K_SAMP; k++) {
            if (pf[k] < 0 || zinv[k] <= lim) continue;
            float ew = __expf((zinv[k] - zm) * INV_GAMMA);
            float prob = 1.0f / (1.0f + __expf(dv[k] * INV_SIGMA));
            float w = prob * ew;

            int ff = pf[k];
            float4 m0 = g_packed[ff * 3 + 0];
            float4 m1 = g_packed[ff * 3 + 1];
            float4 m2 = g_packed[ff * 3 + 2];

            int bk = (pixc * K_SAMP + k) * 3;
            float c0 = bary[bk + 0];
            float c1 = bary[bk + 1];
            float c2 = bary[bk + 2];

            float gx = fmaf(c0, m0.x, fmaf(c1, m1.x, c2 * m2.x));
            float gy = fmaf(c0, m0.y, fmaf(c1, m1.y, c2 * m2.y));
            float gz = fmaf(c0, m0.z, fmaf(c1, m1.z, c2 * m2.z));

            ax = fmaf(w, gx, ax);
            ay = fmaf(w, gy, ay);
            az = fmaf(w, gz, az);
        }
        vx = ax + delta;
        vy = ay + delta;
        vz = az + delta;
    }

    // ---- normalize + map to [0,1], stage in smem ----
    float nn  = fmaf(vx, vx, fmaf(vy, vy, vz * vz));
    float inv = rsqrtf(fmaxf(nn, 1e-24f));
    s[tid * 3 + 0] = fmaf(vx * inv, 0.5f, 0.5f);
    s[tid * 3 + 1] = fmaf(vy * inv, 0.5f, 0.5f);
    s[tid * 3 + 2] = fmaf(vz * inv, 0.5f, 0.5f);

    __syncthreads();

    // ---- coalesced float4 streaming stores: 256*3 floats = 192 float4 ----
    const int NF = BLK * 3;              // 768 floats
    int fbase  = blockIdx.x * NF;
    int ftotal = npix * 3;
    if (fbase + NF <= ftotal) {
        if (tid < NF / 4) {
            __stcs(reinterpret_cast<float4*>(out) + fbase / 4 + tid,
                   reinterpret_cast<const float4*>(s)[tid]);
        }
    } else {
        for (int i = tid; i < NF; i += BLK) {
            int fi = fbase + i;
            if (fi < ftotal) out[fi] = s[i];
        }
    }
}

extern "C" void kernel_launch(void* const* d_in, const int* in_sizes, int n_in,
                              void* d_out, int out_size)
{
    const int*   p2f   = (const int*  )d_in[0];
    const float* bary  = (const float*)d_in[1];
    const float* zbuf  = (const float*)d_in[2];
    const float* dists = (const float*)d_in[3];
    const float* vnorm = (const float*)d_in[4];
    const int*   faces = (const int*  )d_in[5];
    float* out = (float*)d_out;

    int total = in_sizes[5];                 // F*3
    if (total > F_MAX * 3) total = F_MAX * 3;
    int npix = in_sizes[0] / K_SAMP;

    pack_faces_kernel<<<(total + 255) / 256, 256>>>(faces, vnorm, total);

    int blocks = (npix + BLK - 1) / BLK;
    normal_shader_kernel<<<blocks, BLK>>>(p2f, bary, zbuf, dists, out, npix);
}